// round 6
// baseline (speedup 1.0000x reference)
#include <cuda_runtime.h>
#include <cstdint>

constexpr int K  = 4096;
constexpr int N  = 11008;
constexpr int NW = N / 8;        // qzeros columns = 1376
constexpr int WR = K / 8;        // packed weight rows = 512
constexpr int N8 = N / 8;        // 8-column tiles = 1376
constexpr int NTHR = 256;
constexpr int NBLK = WR * N8 / NTHR;   // 704512/256 = 2752, exact

// nib + 2^23, exact in fp32. (w+M) - (z+M) == w - z exactly for 0..15.
#define MAGIC 0x4B000000u

__device__ __forceinline__ float nib2f(unsigned word, int sh) {
    return __uint_as_float(((word >> sh) & 15u) | MAGIC);
}

__global__ __launch_bounds__(NTHR) void dequant_kernel(
    const int*   __restrict__ qweight,  // [K/8, N]
    const int*   __restrict__ qzeros,   // [G, N/8]
    const float* __restrict__ scales,   // [G, N]
    const int*   __restrict__ g_idx,    // [K]
    float*       __restrict__ out)      // [K, N]
{
    const int idx = blockIdx.x * NTHR + threadIdx.x;   // over WR*N8, no tail
    const int wr  = idx / N8;            // packed row 0..511 (const-div -> mul)
    const int n8  = idx - wr * N8;       // 8-col tile 0..1375
    const int n   = n8 * 8;

    // two adjacent packed weight quads: 8 consecutive columns x 8 k-rows.
    // Both LDG.128 issue back-to-back -> MLP_p1 = 2.
    const uint4* qwp = reinterpret_cast<const uint4*>(qweight + (size_t)wr * N + n);
    const uint4 qa = qwp[0];
    const uint4 qb = qwp[1];

    // g_idx sorted: one group spans all 8 k-rows except at <=31/512 word-rows.
    const int g0 = __ldg(g_idx + wr * 8);
    const int g7 = __ldg(g_idx + wr * 8 + 7);

    float* orow = out + (size_t)(wr * 8) * N + n;

    if (g0 == g7) {
        // ---- fast path: one group for all 8 k-rows ----
        // one qzeros word covers exactly this thread's 8 columns
        const unsigned zw = (unsigned)__ldg(qzeros + g0 * NW + n8);
        float fz[8];
#pragma unroll
        for (int c = 0; c < 8; c++) fz[c] = nib2f(zw, 4 * c);

        const float4* scp = reinterpret_cast<const float4*>(scales + (size_t)g0 * N + n);
        const float4 sa = scp[0];
        const float4 sb = scp[1];

#pragma unroll
        for (int j = 0; j < 8; j++) {
            const int sh = 4 * j;
            float4 oa, ob;
            oa.x = sa.x * (nib2f(qa.x, sh) - fz[0]);
            oa.y = sa.y * (nib2f(qa.y, sh) - fz[1]);
            oa.z = sa.z * (nib2f(qa.z, sh) - fz[2]);
            oa.w = sa.w * (nib2f(qa.w, sh) - fz[3]);
            ob.x = sb.x * (nib2f(qb.x, sh) - fz[4]);
            ob.y = sb.y * (nib2f(qb.y, sh) - fz[5]);
            ob.z = sb.z * (nib2f(qb.z, sh) - fz[6]);
            ob.w = sb.w * (nib2f(qb.w, sh) - fz[7]);
            float4* op = reinterpret_cast<float4*>(orow + (size_t)j * N);
            __stcs(op,     oa);
            __stcs(op + 1, ob);
        }
    } else {
        // ---- rare path: group boundary inside this word-row ----
#pragma unroll
        for (int j = 0; j < 8; j++) {
            const int g = __ldg(g_idx + wr * 8 + j);
            const unsigned zw = (unsigned)__ldg(qzeros + g * NW + n8);
            const float4* scp = reinterpret_cast<const float4*>(scales + (size_t)g * N + n);
            const float4 sa = scp[0];
            const float4 sb = scp[1];
            const int sh = 4 * j;
            float4 oa, ob;
            oa.x = sa.x * (nib2f(qa.x, sh) - nib2f(zw, 0));
            oa.y = sa.y * (nib2f(qa.y, sh) - nib2f(zw, 4));
            oa.z = sa.z * (nib2f(qa.z, sh) - nib2f(zw, 8));
            oa.w = sa.w * (nib2f(qa.w, sh) - nib2f(zw, 12));
            ob.x = sb.x * (nib2f(qb.x, sh) - nib2f(zw, 16));
            ob.y = sb.y * (nib2f(qb.y, sh) - nib2f(zw, 20));
            ob.z = sb.z * (nib2f(qb.z, sh) - nib2f(zw, 24));
            ob.w = sb.w * (nib2f(qb.w, sh) - nib2f(zw, 28));
            float4* op = reinterpret_cast<float4*>(orow + (size_t)j * N);
            __stcs(op,     oa);
            __stcs(op + 1, ob);
        }
    }
}

extern "C" void kernel_launch(void* const* d_in, const int* in_sizes, int n_in,
                              void* d_out, int out_size)
{
    const int*   qweight = (const int*)  d_in[0];
    const int*   qzeros  = (const int*)  d_in[1];
    const float* scales  = (const float*)d_in[2];
    const int*   g_idx   = (const int*)  d_in[3];
    float*       out     = (float*)      d_out;

    dequant_kernel<<<NBLK, NTHR>>>(qweight, qzeros, scales, g_idx, out);
}

// round 7
// speedup vs baseline: 1.5227x; 1.5227x over previous
#include <cuda_runtime.h>
#include <cstdint>

constexpr int K  = 4096;
constexpr int N  = 11008;
constexpr int NW = N / 8;        // qzeros columns = 1376
constexpr int WR = K / 8;        // packed weight rows = 512
constexpr int WR2 = WR / 2;      // row-pairs = 256
constexpr int N4 = N / 4;        // float4 columns = 2752

// nib + 2^23, exact in fp32. (w+M) - (z+M) == w - z exactly for 0..15.
#define MAGIC 0x4B000000u

__device__ __forceinline__ float nib2f(unsigned word, int sh) {
    return __uint_as_float(((word >> sh) & 15u) | MAGIC);
}

__global__ __launch_bounds__(256) void dequant_kernel(
    const int*   __restrict__ qweight,  // [K/8, N]
    const int*   __restrict__ qzeros,   // [G, N/8]
    const float* __restrict__ scales,   // [G, N]
    const int*   __restrict__ g_idx,    // [K]
    float*       __restrict__ out)      // [K, N]
{
    const int n4 = blockIdx.x * blockDim.x + threadIdx.x;  // over N/4
    const int wp = blockIdx.y;                             // row-pair 0..255
    if (n4 >= N4) return;
    const int n  = n4 * 4;
    const int wr = wp * 2;      // first packed row of the pair

    // two packed word-rows, SAME 4 columns: both LDG.128 fully coalesced
    // across the warp and front-batched -> MLP_p1 = 2.
    const uint4 qwa = *reinterpret_cast<const uint4*>(qweight + (size_t)wr * N + n);
    const uint4 qwb = *reinterpret_cast<const uint4*>(qweight + (size_t)(wr + 1) * N + n);

    const int zsh = (n & 4) << 2;   // 0 or 16
    const int nz  = n >> 3;         // qzeros column

    // 16 k-rows: one group unless a boundary falls inside (<=31 of 256 pairs)
    const int g0  = __ldg(g_idx + wr * 8);
    const int g15 = __ldg(g_idx + wr * 8 + 15);

    float* orow = out + (size_t)(wr * 8) * N + n;

    if (g0 == g15) {
        // ---- fast path: one group covers all 16 k-rows ----
        const unsigned zw = (unsigned)__ldg(qzeros + g0 * NW + nz);
        const float fz0 = nib2f(zw, zsh + 0);
        const float fz1 = nib2f(zw, zsh + 4);
        const float fz2 = nib2f(zw, zsh + 8);
        const float fz3 = nib2f(zw, zsh + 12);
        const float4 sc = *reinterpret_cast<const float4*>(
                              scales + (size_t)g0 * N + n);

#pragma unroll
        for (int j = 0; j < 8; j++) {
            const int sh = 4 * j;
            float4 o;
            o.x = sc.x * (nib2f(qwa.x, sh) - fz0);
            o.y = sc.y * (nib2f(qwa.y, sh) - fz1);
            o.z = sc.z * (nib2f(qwa.z, sh) - fz2);
            o.w = sc.w * (nib2f(qwa.w, sh) - fz3);
            __stcs(reinterpret_cast<float4*>(orow + (size_t)j * N), o);
        }
#pragma unroll
        for (int j = 0; j < 8; j++) {
            const int sh = 4 * j;
            float4 o;
            o.x = sc.x * (nib2f(qwb.x, sh) - fz0);
            o.y = sc.y * (nib2f(qwb.y, sh) - fz1);
            o.z = sc.z * (nib2f(qwb.z, sh) - fz2);
            o.w = sc.w * (nib2f(qwb.w, sh) - fz3);
            __stcs(reinterpret_cast<float4*>(orow + (size_t)(8 + j) * N), o);
        }
    } else {
        // ---- rare path: group boundary inside this 16-row span ----
#pragma unroll
        for (int j = 0; j < 16; j++) {
            const int g = __ldg(g_idx + wr * 8 + j);
            const unsigned zw = (unsigned)__ldg(qzeros + g * NW + nz);
            const float fz0 = nib2f(zw, zsh + 0);
            const float fz1 = nib2f(zw, zsh + 4);
            const float fz2 = nib2f(zw, zsh + 8);
            const float fz3 = nib2f(zw, zsh + 12);
            const float4 sc = *reinterpret_cast<const float4*>(
                                  scales + (size_t)g * N + n);
            const uint4 qw = (j < 8) ? qwa : qwb;
            const int sh = 4 * (j & 7);
            float4 o;
            o.x = sc.x * (nib2f(qw.x, sh) - fz0);
            o.y = sc.y * (nib2f(qw.y, sh) - fz1);
            o.z = sc.z * (nib2f(qw.z, sh) - fz2);
            o.w = sc.w * (nib2f(qw.w, sh) - fz3);
            __stcs(reinterpret_cast<float4*>(orow + (size_t)j * N), o);
        }
    }
}

extern "C" void kernel_launch(void* const* d_in, const int* in_sizes, int n_in,
                              void* d_out, int out_size)
{
    const int*   qweight = (const int*)  d_in[0];
    const int*   qzeros  = (const int*)  d_in[1];
    const float* scales  = (const float*)d_in[2];
    const int*   g_idx   = (const int*)  d_in[3];
    float*       out     = (float*)      d_out;

    dim3 block(256);
    dim3 grid((N4 + 255) / 256, WR2);
    dequant_kernel<<<grid, block>>>(qweight, qzeros, scales, g_idx, out);
}

// round 9
// speedup vs baseline: 1.7728x; 1.1643x over previous
#include <cuda_runtime.h>
#include <cstdint>

constexpr int K  = 4096;
constexpr int N  = 11008;
constexpr int NW = N / 8;        // qzeros columns = 1376
constexpr int WR = K / 8;        // packed weight rows = 512
constexpr int N4 = N / 4;        // float4 columns = 2752
constexpr int TILE_COLS = 1024;  // floats per output row per CTA (256 thr * 4)

// nib + 2^23, exact in fp32. (w+M) - (z+M) == w - z exactly for 0..15.
#define MAGIC 0x4B000000u

__device__ __forceinline__ float nib2f(unsigned word, int sh) {
    return __uint_as_float(((word >> sh) & 15u) | MAGIC);
}

__global__ __launch_bounds__(256) void dequant_kernel(
    const int*   __restrict__ qweight,  // [K/8, N]
    const int*   __restrict__ qzeros,   // [G, N/8]
    const float* __restrict__ scales,   // [G, N]
    const int*   __restrict__ g_idx,    // [K]
    float*       __restrict__ out)      // [K, N]
{
    // 8 output rows x 1024 floats = 32KB staging tile
    __shared__ alignas(128) float tile[8 * TILE_COLS];

    const int tid = threadIdx.x;
    const int n4  = blockIdx.x * 256 + tid;   // over N/4
    const int wr  = blockIdx.y;               // packed row 0..511
    const int n   = n4 * 4;

    if (n4 < N4) {
        // coalesced packed-weight load: 4 columns x 8 k-rows
        const uint4 qw = *reinterpret_cast<const uint4*>(
                             qweight + (size_t)wr * N + n);

        // group ids for the 8 k-rows (warp-uniform broadcast loads)
        const int4 gi0 = *reinterpret_cast<const int4*>(g_idx + wr * 8);
        const int4 gi1 = *reinterpret_cast<const int4*>(g_idx + wr * 8 + 4);
        const int gs[8] = {gi0.x, gi0.y, gi0.z, gi0.w, gi1.x, gi1.y, gi1.z, gi1.w};

        const int zsh = (n & 4) << 2;   // 0 or 16
        const int nz  = n >> 3;         // qzeros column

        // g_idx sorted -> group constant within the 8-row span except at
        // rare boundaries; hoist zero/scale behind a warp-uniform compare.
        int gcur = -1;
        float4 sc;
        float fz0 = 0.f, fz1 = 0.f, fz2 = 0.f, fz3 = 0.f;

        float* trow = tile + tid * 4;

#pragma unroll
        for (int j = 0; j < 8; j++) {
            const int g = gs[j];
            if (g != gcur) {
                gcur = g;
                const unsigned zw = (unsigned)__ldg(qzeros + g * NW + nz);
                fz0 = nib2f(zw, zsh + 0);
                fz1 = nib2f(zw, zsh + 4);
                fz2 = nib2f(zw, zsh + 8);
                fz3 = nib2f(zw, zsh + 12);
                sc  = *reinterpret_cast<const float4*>(scales + (size_t)g * N + n);
            }
            const int sh = 4 * j;
            float4 o;
            o.x = sc.x * (nib2f(qw.x, sh) - fz0);
            o.y = sc.y * (nib2f(qw.y, sh) - fz1);
            o.z = sc.z * (nib2f(qw.z, sh) - fz2);
            o.w = sc.w * (nib2f(qw.w, sh) - fz3);
            *reinterpret_cast<float4*>(trow + j * TILE_COLS) = o;  // STS.128
        }
    }

    __syncthreads();

    // 8 threads each bulk-copy one staged row (4KB, or 3KB for the ragged
    // last x-block) straight SMEM -> GMEM, bypassing the L1TEX store path.
    if (tid < 8) {
        const int col0 = blockIdx.x * TILE_COLS;
        const int row_floats = (N - col0 < TILE_COLS) ? (N - col0) : TILE_COLS;
        const int row_bytes  = row_floats * 4;          // 4096 or 3072, mult of 16

        float* dst = out + (size_t)(wr * 8 + tid) * N + col0;
        uint32_t src = (uint32_t)__cvta_generic_to_shared(tile + tid * TILE_COLS);

        // order the block's STS (made visible by syncthreads) into the async proxy
        asm volatile("fence.proxy.async;" ::: "memory");
        asm volatile(
            "cp.async.bulk.global.shared::cta.bulk_group [%0], [%1], %2;"
            :: "l"(dst), "r"(src), "r"(row_bytes) : "memory");
        asm volatile("cp.async.bulk.commit_group;" ::: "memory");
        // wait until the bulk engine has READ the tile before SMEM is released
        asm volatile("cp.async.bulk.wait_group.read 0;" ::: "memory");
    }
}

extern "C" void kernel_launch(void* const* d_in, const int* in_sizes, int n_in,
                              void* d_out, int out_size)
{
    const int*   qweight = (const int*)  d_in[0];
    const int*   qzeros  = (const int*)  d_in[1];
    const float* scales  = (const float*)d_in[2];
    const int*   g_idx   = (const int*)  d_in[3];
    float*       out     = (float*)      d_out;

    dim3 block(256);
    dim3 grid((N4 + 255) / 256, WR);   // (11, 512) = 5632 CTAs
    dequant_kernel<<<grid, block>>>(qweight, qzeros, scales, g_idx, out);
}

// round 10
// speedup vs baseline: 2.1608x; 1.2189x over previous
#include <cuda_runtime.h>
#include <cstdint>

constexpr int K  = 4096;
constexpr int N  = 11008;
constexpr int NW = N / 8;        // qzeros columns = 1376
constexpr int WR = K / 8;        // packed weight rows = 512
constexpr int N4 = N / 4;        // float4 columns = 2752

// nib + 2^23, exact in fp32. (w+M) - (z+M) == w - z exactly for 0..15.
#define MAGIC 0x4B000000u

__device__ __forceinline__ float nib2f(unsigned word, int sh) {
    return __uint_as_float(((word >> sh) & 15u) | MAGIC);
}

__global__ __launch_bounds__(256) void dequant_kernel(
    const int*   __restrict__ qweight,  // [K/8, N]
    const int*   __restrict__ qzeros,   // [G, N/8]
    const float* __restrict__ scales,   // [G, N]
    const int*   __restrict__ g_idx,    // [K]
    float*       __restrict__ out)      // [K, N]
{
    const int n4 = blockIdx.x * blockDim.x + threadIdx.x;  // over N/4
    const int wr = blockIdx.y;                             // packed row 0..511
    if (n4 >= N4) return;
    const int n = n4 * 4;

    // 4 packed weight words: 4 consecutive output columns, 8 k-rows each
    const uint4 qw = *reinterpret_cast<const uint4*>(qweight + (size_t)wr * N + n);

    // group ids for the 8 k-rows (warp-uniform broadcast loads)
    const int4 gi0 = *reinterpret_cast<const int4*>(g_idx + wr * 8);
    const int4 gi1 = *reinterpret_cast<const int4*>(g_idx + wr * 8 + 4);
    const int gs[8] = {gi0.x, gi0.y, gi0.z, gi0.w, gi1.x, gi1.y, gi1.z, gi1.w};

    const int zsh = 4 * (n & 7);   // 0 or 16
    const int nz  = n >> 3;        // qzeros column

    float* orow = out + (size_t)wr * 8 * N + n;

    // group-hoisted state: g_idx is sorted, so the group is constant within
    // this 8-row span except at <=31 of 512 word-rows. The check is
    // warp-uniform (same g across the warp) -> cheap uniform branch.
    int gcur = -1;
    float4 sc;
    float fz0 = 0.f, fz1 = 0.f, fz2 = 0.f, fz3 = 0.f;

#pragma unroll
    for (int j = 0; j < 8; j++) {
        const int g = gs[j];
        if (g != gcur) {
            gcur = g;
            const unsigned zw = (unsigned)__ldg(qzeros + g * NW + nz);
            fz0 = nib2f(zw, zsh + 0);
            fz1 = nib2f(zw, zsh + 4);
            fz2 = nib2f(zw, zsh + 8);
            fz3 = nib2f(zw, zsh + 12);
            sc  = *reinterpret_cast<const float4*>(scales + (size_t)g * N + n);
        }

        const int sh = 4 * j;
        float4 o;
        o.x = sc.x * (nib2f(qw.x, sh) - fz0);
        o.y = sc.y * (nib2f(qw.y, sh) - fz1);
        o.z = sc.z * (nib2f(qw.z, sh) - fz2);
        o.w = sc.w * (nib2f(qw.w, sh) - fz3);

        // streaming store: output is never re-read, keep scales in L2
        __stcs(reinterpret_cast<float4*>(orow + (size_t)j * N), o);
    }
}

extern "C" void kernel_launch(void* const* d_in, const int* in_sizes, int n_in,
                              void* d_out, int out_size)
{
    const int*   qweight = (const int*)  d_in[0];
    const int*   qzeros  = (const int*)  d_in[1];
    const float* scales  = (const float*)d_in[2];
    const int*   g_idx   = (const int*)  d_in[3];
    float*       out     = (float*)      d_out;

    dim3 block(256);
    dim3 grid((N4 + 255) / 256, WR);
    dequant_kernel<<<grid, block>>>(qweight, qzeros, scales, g_idx, out);
}